// round 1
// baseline (speedup 1.0000x reference)
#include <cuda_runtime.h>
#include <cuda_bf16.h>
#include <cstddef>

// ---------------------------------------------------------------------------
// MS-SSIM, 32x1x512x512 fp32 pairs, 5 levels, 11x11 Gaussian (sigma=1.5).
// Fused per-level kernel: separable blur of the 5 moment fields in SMEM,
// per-pixel ssim/mcs, block reduction, double atomics into per-level sums.
// ---------------------------------------------------------------------------

#define TILE  32
#define HALO  5
#define SROWS (TILE + 2*HALO)   // 42
#define WIN   11

__constant__ float G11[WIN] = {
    0.00102839f, 0.00759870f, 0.03600080f, 0.10936070f, 0.21300540f,
    0.26601170f,
    0.21300540f, 0.10936070f, 0.03600080f, 0.00759870f, 0.00102839f
};

#define C1F 1.0e-4f   // 0.01^2
#define C2F 9.0e-4f   // 0.03^2

// scratch pyramid buffers (levels 1..4) for both images
// per image: 32 * (256^2 + 128^2 + 64^2 + 32^2) = 32 * 87040 floats
__device__ float g_buf1[32u * 87040u];
__device__ float g_buf2[32u * 87040u];
// [2*level + 0] = ssim sum, [2*level + 1] = mcs sum
__device__ double g_sums[10];

__global__ void zero_sums_kernel(double* sums) {
    int i = threadIdx.x;
    if (i < 10) sums[i] = 0.0;
}

// One pyramid level. grid = (H/32, H/32, 32), block = (32, 8).
__global__ __launch_bounds__(256)
void ssim_level_kernel(const float* __restrict__ img1,
                       const float* __restrict__ img2,
                       int H, double* __restrict__ sums, int level)
{
    __shared__ float s1[SROWS][SROWS + 2];     // 42 x 44
    __shared__ float s2[SROWS][SROWS + 2];
    __shared__ float hb[5][SROWS][TILE + 1];   // 5 x 42 x 33
    __shared__ float wsum[8][2];

    const int tx = threadIdx.x;
    const int ty = threadIdx.y;
    const int b  = blockIdx.z;
    const int x0 = blockIdx.x * TILE - HALO;
    const int y0 = blockIdx.y * TILE - HALO;

    const float* __restrict__ p1 = img1 + (size_t)b * H * H;
    const float* __restrict__ p2 = img2 + (size_t)b * H * H;

    // ---- load 42x42 halo tiles of both images (zero outside = SAME pad) ----
    for (int r = ty; r < SROWS; r += 8) {
        const int gy = y0 + r;
        const bool yok = (gy >= 0) && (gy < H);
        for (int c = tx; c < SROWS; c += TILE) {
            const int gx = x0 + c;
            float v1 = 0.f, v2 = 0.f;
            if (yok && gx >= 0 && gx < H) {
                v1 = p1[(size_t)gy * H + gx];
                v2 = p2[(size_t)gy * H + gx];
            }
            s1[r][c] = v1;
            s2[r][c] = v2;
        }
    }
    __syncthreads();

    // ---- horizontal 11-tap pass for the 5 moment fields ----
    for (int r = ty; r < SROWS; r += 8) {
        float a0 = 0.f, a1 = 0.f, a2 = 0.f, a3 = 0.f, a4 = 0.f;
#pragma unroll
        for (int k = 0; k < WIN; k++) {
            const float w = G11[k];
            const float u = s1[r][tx + k];
            const float v = s2[r][tx + k];
            a0 += w * u;
            a1 += w * v;
            a2 += w * (u * u);
            a3 += w * (v * v);
            a4 += w * (u * v);
        }
        hb[0][r][tx] = a0;
        hb[1][r][tx] = a1;
        hb[2][r][tx] = a2;
        hb[3][r][tx] = a3;
        hb[4][r][tx] = a4;
    }
    __syncthreads();

    // ---- vertical 11-tap pass + per-pixel ssim/mcs ----
    float lssim = 0.f, lmcs = 0.f;
    for (int rr = ty; rr < TILE; rr += 8) {
        float m1 = 0.f, m2 = 0.f, m11 = 0.f, m22 = 0.f, m12 = 0.f;
#pragma unroll
        for (int k = 0; k < WIN; k++) {
            const float w = G11[k];
            m1  += w * hb[0][rr + k][tx];
            m2  += w * hb[1][rr + k][tx];
            m11 += w * hb[2][rr + k][tx];
            m22 += w * hb[3][rr + k][tx];
            m12 += w * hb[4][rr + k][tx];
        }
        const float mu1sq = m1 * m1;
        const float mu2sq = m2 * m2;
        const float mu12  = m1 * m2;
        const float sig1  = m11 - mu1sq;
        const float sig2  = m22 - mu2sq;
        const float sig12 = m12 - mu12;
        const float mcs   = (2.f * sig12 + C2F) / (sig1 + sig2 + C2F);
        const float ssim  = ((2.f * mu12 + C1F) / (mu1sq + mu2sq + C1F)) * mcs;
        lssim += ssim;
        lmcs  += mcs;
    }

    // ---- block reduction (warp shuffle + smem) ----
#pragma unroll
    for (int o = 16; o > 0; o >>= 1) {
        lssim += __shfl_down_sync(0xffffffffu, lssim, o);
        lmcs  += __shfl_down_sync(0xffffffffu, lmcs,  o);
    }
    if (tx == 0) {
        wsum[ty][0] = lssim;
        wsum[ty][1] = lmcs;
    }
    __syncthreads();
    if (ty == 0 && tx < 8) {
        float a = wsum[tx][0];
        float c = wsum[tx][1];
#pragma unroll
        for (int o = 4; o > 0; o >>= 1) {
            a += __shfl_down_sync(0xffu, a, o);
            c += __shfl_down_sync(0xffu, c, o);
        }
        if (tx == 0) {
            atomicAdd(&sums[2 * level + 0], (double)a);
            atomicAdd(&sums[2 * level + 1], (double)c);
        }
    }
}

// 2x2 average pool for both images; Ho = output H (=W).
__global__ void down2_kernel(const float* __restrict__ a,
                             const float* __restrict__ b,
                             float* __restrict__ oa,
                             float* __restrict__ ob, int Ho)
{
    const int n = 32 * Ho * Ho;
    int i = blockIdx.x * blockDim.x + threadIdx.x;
    if (i >= n) return;
    const int img = i / (Ho * Ho);
    const int rem = i - img * (Ho * Ho);
    const int y = rem / Ho;
    const int x = rem - y * Ho;
    const int Hi = 2 * Ho;
    const size_t base = (size_t)img * Hi * Hi + (size_t)(2 * y) * Hi + 2 * x;

    oa[i] = 0.25f * (a[base] + a[base + 1] + a[base + Hi] + a[base + Hi + 1]);
    ob[i] = 0.25f * (b[base] + b[base + 1] + b[base + Hi] + b[base + Hi + 1]);
}

__global__ void finalize_kernel(const double* __restrict__ sums,
                                float* __restrict__ out)
{
    const double w[5] = {0.0448, 0.2856, 0.3001, 0.2363, 0.1333};
    double res = 1.0;
#pragma unroll
    for (int l = 0; l < 4; l++) {
        const double dim = (double)(512 >> l);
        const double N = 32.0 * dim * dim;
        const double mcs = sums[2 * l + 1] / N;
        res *= pow(mcs, w[l]);
    }
    {
        const double dim = 32.0;
        const double N = 32.0 * dim * dim;
        const double ssim = sums[2 * 4 + 0] / N;
        res *= pow(ssim, w[4]);
    }
    out[0] = (float)res;
}

extern "C" void kernel_launch(void* const* d_in, const int* in_sizes, int n_in,
                              void* d_out, int out_size)
{
    const float* img1 = (const float*)d_in[0];
    const float* img2 = (const float*)d_in[1];
    float* out = (float*)d_out;

    double* sums = nullptr;
    float*  buf1 = nullptr;
    float*  buf2 = nullptr;
    cudaGetSymbolAddress((void**)&sums, g_sums);
    cudaGetSymbolAddress((void**)&buf1, g_buf1);
    cudaGetSymbolAddress((void**)&buf2, g_buf2);

    // scratch offsets for levels 1..4 (per image)
    const size_t off1 = 0;
    const size_t off2 = off1 + (size_t)32 * 256 * 256;
    const size_t off3 = off2 + (size_t)32 * 128 * 128;
    const size_t off4 = off3 + (size_t)32 * 64 * 64;

    const dim3 blk(32, 8);

    zero_sums_kernel<<<1, 32>>>(sums);

    // level 0 (512)
    ssim_level_kernel<<<dim3(16, 16, 32), blk>>>(img1, img2, 512, sums, 0);
    {
        int n = 32 * 256 * 256;
        down2_kernel<<<(n + 255) / 256, 256>>>(img1, img2, buf1 + off1, buf2 + off1, 256);
    }
    // level 1 (256)
    ssim_level_kernel<<<dim3(8, 8, 32), blk>>>(buf1 + off1, buf2 + off1, 256, sums, 1);
    {
        int n = 32 * 128 * 128;
        down2_kernel<<<(n + 255) / 256, 256>>>(buf1 + off1, buf2 + off1, buf1 + off2, buf2 + off2, 128);
    }
    // level 2 (128)
    ssim_level_kernel<<<dim3(4, 4, 32), blk>>>(buf1 + off2, buf2 + off2, 128, sums, 2);
    {
        int n = 32 * 64 * 64;
        down2_kernel<<<(n + 255) / 256, 256>>>(buf1 + off2, buf2 + off2, buf1 + off3, buf2 + off3, 64);
    }
    // level 3 (64)
    ssim_level_kernel<<<dim3(2, 2, 32), blk>>>(buf1 + off3, buf2 + off3, 64, sums, 3);
    {
        int n = 32 * 32 * 32;
        down2_kernel<<<(n + 255) / 256, 256>>>(buf1 + off3, buf2 + off3, buf1 + off4, buf2 + off4, 32);
    }
    // level 4 (32)
    ssim_level_kernel<<<dim3(1, 1, 32), blk>>>(buf1 + off4, buf2 + off4, 32, sums, 4);

    finalize_kernel<<<1, 1>>>(sums, out);
}

// round 2
// speedup vs baseline: 1.3382x; 1.3382x over previous
#include <cuda_runtime.h>
#include <cuda_bf16.h>
#include <cstddef>

// ---------------------------------------------------------------------------
// MS-SSIM, 32x1x512x512 fp32 pairs, 5 levels, 11x11 Gaussian (sigma=1.5).
// Fused per-level kernel with register-reuse separable blur (4 consecutive
// outputs per thread in each pass) + fused 2x2 downsample for the next level.
// ---------------------------------------------------------------------------

#define TILE  32
#define HALO  5
#define SROWS (TILE + 2*HALO)   // 42
#define SSTR  43                // s1/s2 row stride (conflict-free)
#define HSTR  33                // hb row stride (conflict-free)
#define WIN   11

__constant__ float G11[WIN] = {
    0.00102839f, 0.00759870f, 0.03600080f, 0.10936070f, 0.21300540f,
    0.26601170f,
    0.21300540f, 0.10936070f, 0.03600080f, 0.00759870f, 0.00102839f
};

#define C1F 1.0e-4f   // 0.01^2
#define C2F 9.0e-4f   // 0.03^2

__device__ float g_buf1[32u * 87040u];
__device__ float g_buf2[32u * 87040u];
__device__ double g_sums[10];

__global__ void zero_sums_kernel(double* sums) {
    int i = threadIdx.x;
    if (i < 10) sums[i] = 0.0;
}

__global__ __launch_bounds__(256, 4)
void ssim_level_kernel(const float* __restrict__ img1,
                       const float* __restrict__ img2,
                       int H, double* __restrict__ sums, int level,
                       float* __restrict__ o1, float* __restrict__ o2)
{
    __shared__ float s1[SROWS][SSTR];
    __shared__ float s2[SROWS][SSTR];
    __shared__ float hb[5][SROWS][HSTR];
    __shared__ float wsum[8][2];

    const int tx  = threadIdx.x;
    const int ty  = threadIdx.y;
    const int tid = ty * 32 + tx;
    const int b   = blockIdx.z;
    const int x0  = blockIdx.x * TILE - HALO;
    const int y0  = blockIdx.y * TILE - HALO;

    const float* __restrict__ p1 = img1 + (size_t)b * H * H;
    const float* __restrict__ p2 = img2 + (size_t)b * H * H;

    const bool interior = (x0 >= 0) && (y0 >= 0) &&
                          (x0 + SROWS <= H) && (y0 + SROWS <= H);
    if (interior) {
        for (int r = ty; r < SROWS; r += 8) {
            const size_t row = (size_t)(y0 + r) * H + x0;
#pragma unroll
            for (int c = tx; c < SROWS; c += TILE) {
                s1[r][c] = p1[row + c];
                s2[r][c] = p2[row + c];
            }
        }
    } else {
        for (int r = ty; r < SROWS; r += 8) {
            const int gy = y0 + r;
            const bool yok = (gy >= 0) && (gy < H);
#pragma unroll
            for (int c = tx; c < SROWS; c += TILE) {
                const int gx = x0 + c;
                float v1 = 0.f, v2 = 0.f;
                if (yok && gx >= 0 && gx < H) {
                    v1 = p1[(size_t)gy * H + gx];
                    v2 = p2[(size_t)gy * H + gx];
                }
                s1[r][c] = v1;
                s2[r][c] = v2;
            }
        }
    }
    __syncthreads();

    // horizontal pass: 42 rows x 8 col-groups of 4 = 336 tasks
    for (int t = tid; t < SROWS * 8; t += 256) {
        const int r  = t >> 3;
        const int cg = (t & 7) << 2;
        const float* __restrict__ b1 = &s1[r][cg];
        const float* __restrict__ b2 = &s2[r][cg];

        float a0[4] = {0.f, 0.f, 0.f, 0.f};
        float a1[4] = {0.f, 0.f, 0.f, 0.f};
        float a2[4] = {0.f, 0.f, 0.f, 0.f};
        float a3[4] = {0.f, 0.f, 0.f, 0.f};
        float a4[4] = {0.f, 0.f, 0.f, 0.f};
#pragma unroll
        for (int i = 0; i < 14; i++) {
            const float u  = b1[i];
            const float v  = b2[i];
            const float uu = u * u;
            const float vv = v * v;
            const float uv = u * v;
#pragma unroll
            for (int j = 0; j < 4; j++) {
                const int k = i - j;
                if (k >= 0 && k < WIN) {
                    const float w = G11[k];
                    a0[j] = fmaf(w, u,  a0[j]);
                    a1[j] = fmaf(w, v,  a1[j]);
                    a2[j] = fmaf(w, uu, a2[j]);
                    a3[j] = fmaf(w, vv, a3[j]);
                    a4[j] = fmaf(w, uv, a4[j]);
                }
            }
        }
#pragma unroll
        for (int j = 0; j < 4; j++) {
            hb[0][r][cg + j] = a0[j];
            hb[1][r][cg + j] = a1[j];
            hb[2][r][cg + j] = a2[j];
            hb[3][r][cg + j] = a3[j];
            hb[4][r][cg + j] = a4[j];
        }
    }
    __syncthreads();

    // vertical pass: thread = col tx, rows 4*ty .. 4*ty+3
    float acc[5][4];
#pragma unroll
    for (int f = 0; f < 5; f++)
#pragma unroll
        for (int j = 0; j < 4; j++) acc[f][j] = 0.f;

    const int r0 = ty << 2;
#pragma unroll
    for (int f = 0; f < 5; f++) {
#pragma unroll
        for (int i = 0; i < 14; i++) {
            const float val = hb[f][r0 + i][tx];
#pragma unroll
            for (int j = 0; j < 4; j++) {
                const int k = i - j;
                if (k >= 0 && k < WIN)
                    acc[f][j] = fmaf(G11[k], val, acc[f][j]);
            }
        }
    }

    float lssim = 0.f, lmcs = 0.f;
#pragma unroll
    for (int j = 0; j < 4; j++) {
        const float m1  = acc[0][j];
        const float m2  = acc[1][j];
        const float m11 = acc[2][j];
        const float m22 = acc[3][j];
        const float m12 = acc[4][j];
        const float mu1sq = m1 * m1;
        const float mu2sq = m2 * m2;
        const float mu12  = m1 * m2;
        const float sig1  = m11 - mu1sq;
        const float sig2  = m22 - mu2sq;
        const float sig12 = m12 - mu12;
        const float mcs  = __fdividef(2.f * sig12 + C2F, sig1 + sig2 + C2F);
        const float ssim = __fdividef(2.f * mu12 + C1F, mu1sq + mu2sq + C1F) * mcs;
        lssim += ssim;
        lmcs  += mcs;
    }

    // fused 2x2 avg-pool for next level
    if (o1 != nullptr) {
        const int Ho = H >> 1;
        const int ly = tid >> 4;
        const int lx = tid & 15;
        const int sy = HALO + (ly << 1);
        const int sx = HALO + (lx << 1);
        const float d1 = 0.25f * (s1[sy][sx] + s1[sy][sx + 1] +
                                  s1[sy + 1][sx] + s1[sy + 1][sx + 1]);
        const float d2 = 0.25f * (s2[sy][sx] + s2[sy][sx + 1] +
                                  s2[sy + 1][sx] + s2[sy + 1][sx + 1]);
        const int oy = blockIdx.y * 16 + ly;
        const int ox = blockIdx.x * 16 + lx;
        const size_t oidx = ((size_t)b * Ho + oy) * Ho + ox;
        o1[oidx] = d1;
        o2[oidx] = d2;
    }

    // block reduction
#pragma unroll
    for (int o = 16; o > 0; o >>= 1) {
        lssim += __shfl_down_sync(0xffffffffu, lssim, o);
        lmcs  += __shfl_down_sync(0xffffffffu, lmcs,  o);
    }
    if (tx == 0) {
        wsum[ty][0] = lssim;
        wsum[ty][1] = lmcs;
    }
    __syncthreads();
    if (ty == 0 && tx < 8) {
        float a = wsum[tx][0];
        float c = wsum[tx][1];
#pragma unroll
        for (int o = 4; o > 0; o >>= 1) {
            a += __shfl_down_sync(0xffu, a, o);
            c += __shfl_down_sync(0xffu, c, o);
        }
        if (tx == 0) {
            atomicAdd(&sums[2 * level + 0], (double)a);
            atomicAdd(&sums[2 * level + 1], (double)c);
        }
    }
}

__global__ void finalize_kernel(const double* __restrict__ sums,
                                float* __restrict__ out)
{
    const double w[5] = {0.0448, 0.2856, 0.3001, 0.2363, 0.1333};
    double res = 1.0;
#pragma unroll
    for (int l = 0; l < 4; l++) {
        const double dim = (double)(512 >> l);
        const double N = 32.0 * dim * dim;
        const double mcs = sums[2 * l + 1] / N;
        res *= pow(mcs, w[l]);
    }
    {
        const double N = 32.0 * 32.0 * 32.0;
        const double ssim = sums[2 * 4 + 0] / N;
        res *= pow(ssim, w[4]);
    }
    out[0] = (float)res;
}

extern "C" void kernel_launch(void* const* d_in, const int* in_sizes, int n_in,
                              void* d_out, int out_size)
{
    const float* img1 = (const float*)d_in[0];
    const float* img2 = (const float*)d_in[1];
    float* out = (float*)d_out;

    double* sums = nullptr;
    float*  buf1 = nullptr;
    float*  buf2 = nullptr;
    cudaGetSymbolAddress((void**)&sums, g_sums);
    cudaGetSymbolAddress((void**)&buf1, g_buf1);
    cudaGetSymbolAddress((void**)&buf2, g_buf2);

    const size_t off1 = 0;
    const size_t off2 = off1 + (size_t)32 * 256 * 256;
    const size_t off3 = off2 + (size_t)32 * 128 * 128;
    const size_t off4 = off3 + (size_t)32 * 64 * 64;

    const dim3 blk(32, 8);

    zero_sums_kernel<<<1, 32>>>(sums);

    ssim_level_kernel<<<dim3(16, 16, 32), blk>>>(img1, img2, 512, sums, 0,
                                                 buf1 + off1, buf2 + off1);
    ssim_level_kernel<<<dim3(8, 8, 32), blk>>>(buf1 + off1, buf2 + off1, 256, sums, 1,
                                               buf1 + off2, buf2 + off2);
    ssim_level_kernel<<<dim3(4, 4, 32), blk>>>(buf1 + off2, buf2 + off2, 128, sums, 2,
                                               buf1 + off3, buf2 + off3);
    ssim_level_kernel<<<dim3(2, 2, 32), blk>>>(buf1 + off3, buf2 + off3, 64, sums, 3,
                                               buf1 + off4, buf2 + off4);
    ssim_level_kernel<<<dim3(1, 1, 32), blk>>>(buf1 + off4, buf2 + off4, 32, sums, 4,
                                               nullptr, nullptr);

    finalize_kernel<<<1, 1>>>(sums, out);
}

// round 3
// speedup vs baseline: 1.4891x; 1.1128x over previous
#include <cuda_runtime.h>
#include <cuda_bf16.h>
#include <cstddef>

// ---------------------------------------------------------------------------
// MS-SSIM, 32x1x512x512 fp32 pairs, 5 levels, 11x11 Gaussian (sigma=1.5).
// 3 launches:
//   1) pyramid_kernel: builds levels 1..4 hierarchically (one block = one
//      64x64 tile of the original, pooled down in SMEM) + zeroes accumulators.
//   2) ssim_all_kernel: ALL five levels in one flat grid (10912 blocks).
//   3) finalize_kernel.
// ---------------------------------------------------------------------------

#define TILE  32
#define HALO  5
#define SROWS (TILE + 2*HALO)   // 42
#define SSTR  43                // s1/s2 row stride (conflict-free)
#define HSTR  33                // hb row stride (conflict-free)
#define WIN   11

__constant__ float G11[WIN] = {
    0.00102839f, 0.00759870f, 0.03600080f, 0.10936070f, 0.21300540f,
    0.26601170f,
    0.21300540f, 0.10936070f, 0.03600080f, 0.00759870f, 0.00102839f
};

#define C1F 1.0e-4f   // 0.01^2
#define C2F 9.0e-4f   // 0.03^2

// pyramid scratch, per image: 32 * (256^2 + 128^2 + 64^2 + 32^2)
#define OFF1 ((size_t)0)
#define OFF2 (OFF1 + (size_t)32 * 256 * 256)
#define OFF3 (OFF2 + (size_t)32 * 128 * 128)
#define OFF4 (OFF3 + (size_t)32 * 64 * 64)

__device__ float g_buf1[32u * 87040u];
__device__ float g_buf2[32u * 87040u];
__device__ double g_sums[10];   // [2*level] = ssim sum, [2*level+1] = mcs sum

// ---------------------------------------------------------------------------
// Pyramid builder: grid (8, 8, 32), block 256.
// Each block: 64x64 tile of the original -> 32x32 (L1) -> 16x16 (L2)
// -> 8x8 (L3) -> 4x4 (L4), all written to global scratch.
// ---------------------------------------------------------------------------
__global__ __launch_bounds__(256)
void pyramid_kernel(const float* __restrict__ img1,
                    const float* __restrict__ img2,
                    float* __restrict__ buf1,
                    float* __restrict__ buf2,
                    double* __restrict__ sums)
{
    __shared__ float t1[64][65], t2[64][65];
    __shared__ float a1[32][33], a2[32][33];
    __shared__ float e1[16][17], e2[16][17];
    __shared__ float c1[8][9],  c2[8][9];

    const int tid = threadIdx.x;
    const int bx = blockIdx.x, by = blockIdx.y, b = blockIdx.z;

    if (bx == 0 && by == 0 && b == 0 && tid < 10) sums[tid] = 0.0;

    const float* __restrict__ p1 = img1 + (size_t)b * 512 * 512;
    const float* __restrict__ p2 = img2 + (size_t)b * 512 * 512;

    // load 64x64 tile (float4 vectorized; tile origin is 64-aligned)
#pragma unroll
    for (int it = 0; it < 4; it++) {
        const int r  = (tid >> 4) + 16 * it;
        const int c4 = tid & 15;
        const size_t rowoff = (size_t)(by * 64 + r) * 512 + bx * 64;
        const float4 v1 = *(const float4*)(p1 + rowoff + c4 * 4);
        const float4 v2 = *(const float4*)(p2 + rowoff + c4 * 4);
        t1[r][c4 * 4 + 0] = v1.x; t1[r][c4 * 4 + 1] = v1.y;
        t1[r][c4 * 4 + 2] = v1.z; t1[r][c4 * 4 + 3] = v1.w;
        t2[r][c4 * 4 + 0] = v2.x; t2[r][c4 * 4 + 1] = v2.y;
        t2[r][c4 * 4 + 2] = v2.z; t2[r][c4 * 4 + 3] = v2.w;
    }
    __syncthreads();

    // pool -> 32x32 (level 1)
#pragma unroll
    for (int it = 0; it < 4; it++) {
        const int o  = tid + 256 * it;
        const int oy = o >> 5, ox = o & 31;
        const float d1 = 0.25f * (t1[2*oy][2*ox] + t1[2*oy][2*ox+1] +
                                  t1[2*oy+1][2*ox] + t1[2*oy+1][2*ox+1]);
        const float d2 = 0.25f * (t2[2*oy][2*ox] + t2[2*oy][2*ox+1] +
                                  t2[2*oy+1][2*ox] + t2[2*oy+1][2*ox+1]);
        a1[oy][ox] = d1;
        a2[oy][ox] = d2;
        const size_t gi = ((size_t)b * 256 + (by * 32 + oy)) * 256 + (bx * 32 + ox);
        buf1[OFF1 + gi] = d1;
        buf2[OFF1 + gi] = d2;
    }
    __syncthreads();

    // pool -> 16x16 (level 2)
    {
        const int oy = tid >> 4, ox = tid & 15;   // 256 threads = 256 outputs
        const float d1 = 0.25f * (a1[2*oy][2*ox] + a1[2*oy][2*ox+1] +
                                  a1[2*oy+1][2*ox] + a1[2*oy+1][2*ox+1]);
        const float d2 = 0.25f * (a2[2*oy][2*ox] + a2[2*oy][2*ox+1] +
                                  a2[2*oy+1][2*ox] + a2[2*oy+1][2*ox+1]);
        e1[oy][ox] = d1;
        e2[oy][ox] = d2;
        const size_t gi = ((size_t)b * 128 + (by * 16 + oy)) * 128 + (bx * 16 + ox);
        buf1[OFF2 + gi] = d1;
        buf2[OFF2 + gi] = d2;
    }
    __syncthreads();

    // pool -> 8x8 (level 3)
    if (tid < 64) {
        const int oy = tid >> 3, ox = tid & 7;
        const float d1 = 0.25f * (e1[2*oy][2*ox] + e1[2*oy][2*ox+1] +
                                  e1[2*oy+1][2*ox] + e1[2*oy+1][2*ox+1]);
        const float d2 = 0.25f * (e2[2*oy][2*ox] + e2[2*oy][2*ox+1] +
                                  e2[2*oy+1][2*ox] + e2[2*oy+1][2*ox+1]);
        c1[oy][ox] = d1;
        c2[oy][ox] = d2;
        const size_t gi = ((size_t)b * 64 + (by * 8 + oy)) * 64 + (bx * 8 + ox);
        buf1[OFF3 + gi] = d1;
        buf2[OFF3 + gi] = d2;
    }
    __syncthreads();

    // pool -> 4x4 (level 4)
    if (tid < 16) {
        const int oy = tid >> 2, ox = tid & 3;
        const float d1 = 0.25f * (c1[2*oy][2*ox] + c1[2*oy][2*ox+1] +
                                  c1[2*oy+1][2*ox] + c1[2*oy+1][2*ox+1]);
        const float d2 = 0.25f * (c2[2*oy][2*ox] + c2[2*oy][2*ox+1] +
                                  c2[2*oy+1][2*ox] + c2[2*oy+1][2*ox+1]);
        const size_t gi = ((size_t)b * 32 + (by * 4 + oy)) * 32 + (bx * 4 + ox);
        buf1[OFF4 + gi] = d1;
        buf2[OFF4 + gi] = d2;
    }
}

// ---------------------------------------------------------------------------
// All 5 SSIM levels, one flat grid. Block (32,8).
// Level block ranges: L0 [0,8192) L1 [8192,10240) L2 [10240,10752)
//                     L3 [10752,10880) L4 [10880,10912)
// ---------------------------------------------------------------------------
__global__ __launch_bounds__(256, 5)
void ssim_all_kernel(const float* __restrict__ img1,
                     const float* __restrict__ img2,
                     const float* __restrict__ buf1,
                     const float* __restrict__ buf2,
                     double* __restrict__ sums)
{
    __shared__ float s1[SROWS][SSTR];
    __shared__ float s2[SROWS][SSTR];
    __shared__ float hb[5][SROWS][HSTR];
    __shared__ float wsum[8][2];

    const int tx  = threadIdx.x;
    const int ty  = threadIdx.y;
    const int tid = ty * 32 + tx;

    // decode level + tile coordinates from flat block id
    const int gb = blockIdx.x;
    int level, start;
    const float *p1base, *p2base;
    if (gb < 8192)       { level = 0; start = 0;     p1base = img1;        p2base = img2;        }
    else if (gb < 10240) { level = 1; start = 8192;  p1base = buf1 + OFF1; p2base = buf2 + OFF1; }
    else if (gb < 10752) { level = 2; start = 10240; p1base = buf1 + OFF2; p2base = buf2 + OFF2; }
    else if (gb < 10880) { level = 3; start = 10752; p1base = buf1 + OFF3; p2base = buf2 + OFF3; }
    else                 { level = 4; start = 10880; p1base = buf1 + OFF4; p2base = buf2 + OFF4; }

    const int shift = 4 - level;          // log2(nbx)
    const int nbx   = 1 << shift;
    const int H     = 512 >> level;
    const int idx   = gb - start;
    const int b     = idx >> (2 * shift);
    const int rem   = idx & ((1 << (2 * shift)) - 1);
    const int byi   = rem >> shift;
    const int bxi   = rem & (nbx - 1);

    const int x0 = bxi * TILE - HALO;
    const int y0 = byi * TILE - HALO;

    const float* __restrict__ p1 = p1base + (size_t)b * H * H;
    const float* __restrict__ p2 = p2base + (size_t)b * H * H;

    // ---- load 42x42 halo tiles (zero pad outside = SAME) ----
    const bool interior = (x0 >= 0) && (y0 >= 0) &&
                          (x0 + SROWS <= H) && (y0 + SROWS <= H);
    if (interior) {
        for (int r = ty; r < SROWS; r += 8) {
            const size_t row = (size_t)(y0 + r) * H + x0;
#pragma unroll
            for (int c = tx; c < SROWS; c += TILE) {
                s1[r][c] = p1[row + c];
                s2[r][c] = p2[row + c];
            }
        }
    } else {
        for (int r = ty; r < SROWS; r += 8) {
            const int gy = y0 + r;
            const bool yok = (gy >= 0) && (gy < H);
#pragma unroll
            for (int c = tx; c < SROWS; c += TILE) {
                const int gx = x0 + c;
                float v1 = 0.f, v2 = 0.f;
                if (yok && gx >= 0 && gx < H) {
                    v1 = p1[(size_t)gy * H + gx];
                    v2 = p2[(size_t)gy * H + gx];
                }
                s1[r][c] = v1;
                s2[r][c] = v2;
            }
        }
    }
    __syncthreads();

    // ---- horizontal 11-tap pass: 42 rows x 8 col-groups of 4 ----
    for (int t = tid; t < SROWS * 8; t += 256) {
        const int r  = t >> 3;
        const int cg = (t & 7) << 2;
        const float* __restrict__ b1 = &s1[r][cg];
        const float* __restrict__ b2 = &s2[r][cg];

        float a0[4] = {0.f, 0.f, 0.f, 0.f};
        float a1[4] = {0.f, 0.f, 0.f, 0.f};
        float a2[4] = {0.f, 0.f, 0.f, 0.f};
        float a3[4] = {0.f, 0.f, 0.f, 0.f};
        float a4[4] = {0.f, 0.f, 0.f, 0.f};
#pragma unroll
        for (int i = 0; i < 14; i++) {
            const float u  = b1[i];
            const float v  = b2[i];
            const float uu = u * u;
            const float vv = v * v;
            const float uv = u * v;
#pragma unroll
            for (int j = 0; j < 4; j++) {
                const int k = i - j;
                if (k >= 0 && k < WIN) {
                    const float w = G11[k];
                    a0[j] = fmaf(w, u,  a0[j]);
                    a1[j] = fmaf(w, v,  a1[j]);
                    a2[j] = fmaf(w, uu, a2[j]);
                    a3[j] = fmaf(w, vv, a3[j]);
                    a4[j] = fmaf(w, uv, a4[j]);
                }
            }
        }
#pragma unroll
        for (int j = 0; j < 4; j++) {
            hb[0][r][cg + j] = a0[j];
            hb[1][r][cg + j] = a1[j];
            hb[2][r][cg + j] = a2[j];
            hb[3][r][cg + j] = a3[j];
            hb[4][r][cg + j] = a4[j];
        }
    }
    __syncthreads();

    // ---- vertical 11-tap pass: thread = col tx, rows 4*ty .. 4*ty+3 ----
    float acc[5][4];
#pragma unroll
    for (int f = 0; f < 5; f++)
#pragma unroll
        for (int j = 0; j < 4; j++) acc[f][j] = 0.f;

    const int r0 = ty << 2;
#pragma unroll
    for (int f = 0; f < 5; f++) {
#pragma unroll
        for (int i = 0; i < 14; i++) {
            const float val = hb[f][r0 + i][tx];
#pragma unroll
            for (int j = 0; j < 4; j++) {
                const int k = i - j;
                if (k >= 0 && k < WIN)
                    acc[f][j] = fmaf(G11[k], val, acc[f][j]);
            }
        }
    }

    float lssim = 0.f, lmcs = 0.f;
#pragma unroll
    for (int j = 0; j < 4; j++) {
        const float m1  = acc[0][j];
        const float m2  = acc[1][j];
        const float m11 = acc[2][j];
        const float m22 = acc[3][j];
        const float m12 = acc[4][j];
        const float mu1sq = m1 * m1;
        const float mu2sq = m2 * m2;
        const float mu12  = m1 * m2;
        const float sig1  = m11 - mu1sq;
        const float sig2  = m22 - mu2sq;
        const float sig12 = m12 - mu12;
        const float mcs  = __fdividef(2.f * sig12 + C2F, sig1 + sig2 + C2F);
        const float ssim = __fdividef(2.f * mu12 + C1F, mu1sq + mu2sq + C1F) * mcs;
        lssim += ssim;
        lmcs  += mcs;
    }

    // ---- block reduction + per-level double atomics ----
#pragma unroll
    for (int o = 16; o > 0; o >>= 1) {
        lssim += __shfl_down_sync(0xffffffffu, lssim, o);
        lmcs  += __shfl_down_sync(0xffffffffu, lmcs,  o);
    }
    if (tx == 0) {
        wsum[ty][0] = lssim;
        wsum[ty][1] = lmcs;
    }
    __syncthreads();
    if (ty == 0 && tx < 8) {
        float a = wsum[tx][0];
        float c = wsum[tx][1];
#pragma unroll
        for (int o = 4; o > 0; o >>= 1) {
            a += __shfl_down_sync(0xffu, a, o);
            c += __shfl_down_sync(0xffu, c, o);
        }
        if (tx == 0) {
            atomicAdd(&sums[2 * level + 0], (double)a);
            atomicAdd(&sums[2 * level + 1], (double)c);
        }
    }
}

__global__ void finalize_kernel(const double* __restrict__ sums,
                                float* __restrict__ out)
{
    const double w[5] = {0.0448, 0.2856, 0.3001, 0.2363, 0.1333};
    double res = 1.0;
#pragma unroll
    for (int l = 0; l < 4; l++) {
        const double dim = (double)(512 >> l);
        const double N = 32.0 * dim * dim;
        const double mcs = sums[2 * l + 1] / N;
        res *= pow(mcs, w[l]);
    }
    {
        const double N = 32.0 * 32.0 * 32.0;
        const double ssim = sums[2 * 4 + 0] / N;
        res *= pow(ssim, w[4]);
    }
    out[0] = (float)res;
}

extern "C" void kernel_launch(void* const* d_in, const int* in_sizes, int n_in,
                              void* d_out, int out_size)
{
    const float* img1 = (const float*)d_in[0];
    const float* img2 = (const float*)d_in[1];
    float* out = (float*)d_out;

    double* sums = nullptr;
    float*  buf1 = nullptr;
    float*  buf2 = nullptr;
    cudaGetSymbolAddress((void**)&sums, g_sums);
    cudaGetSymbolAddress((void**)&buf1, g_buf1);
    cudaGetSymbolAddress((void**)&buf2, g_buf2);

    pyramid_kernel<<<dim3(8, 8, 32), 256>>>(img1, img2, buf1, buf2, sums);
    ssim_all_kernel<<<10912, dim3(32, 8)>>>(img1, img2, buf1, buf2, sums);
    finalize_kernel<<<1, 1>>>(sums, out);
}

// round 4
// speedup vs baseline: 1.7127x; 1.1501x over previous
#include <cuda_runtime.h>
#include <cuda_bf16.h>
#include <cstddef>

// ---------------------------------------------------------------------------
// MS-SSIM, 32x1x512x512 fp32 pairs, 5 levels, 11x11 Gaussian (sigma=1.5).
// 3 launches:
//   1) pyramid_kernel: builds levels 1..4 + zeroes accumulators.
//   2) ssim_all_kernel: ALL five levels, one flat grid, f32x2-packed math.
//   3) finalize_kernel.
// ---------------------------------------------------------------------------

#define TILE  32
#define HALO  5
#define SROWS (TILE + 2*HALO)   // 42
#define SSTR  43                // s12 row stride (float2 units)
#define HSTR  33                // hb row stride
#define WIN   11

typedef unsigned long long u64;

__constant__ float G11[WIN] = {
    0.00102839f, 0.00759870f, 0.03600080f, 0.10936070f, 0.21300540f,
    0.26601170f,
    0.21300540f, 0.10936070f, 0.03600080f, 0.00759870f, 0.00102839f
};
// packed {w, w} pairs for f32x2 math
__constant__ float2 G2[WIN] = {
    {0.00102839f, 0.00102839f}, {0.00759870f, 0.00759870f},
    {0.03600080f, 0.03600080f}, {0.10936070f, 0.10936070f},
    {0.21300540f, 0.21300540f}, {0.26601170f, 0.26601170f},
    {0.21300540f, 0.21300540f}, {0.10936070f, 0.10936070f},
    {0.03600080f, 0.03600080f}, {0.00759870f, 0.00759870f},
    {0.00102839f, 0.00102839f}
};

#define C1F 1.0e-4f   // 0.01^2
#define C2F 9.0e-4f   // 0.03^2

#define OFF1 ((size_t)0)
#define OFF2 (OFF1 + (size_t)32 * 256 * 256)
#define OFF3 (OFF2 + (size_t)32 * 128 * 128)
#define OFF4 (OFF3 + (size_t)32 * 64 * 64)

__device__ float g_buf1[32u * 87040u];
__device__ float g_buf2[32u * 87040u];
__device__ double g_sums[10];

// ---- f32x2 packed helpers -------------------------------------------------
__device__ __forceinline__ void fma2(u64& d, u64 a, u64 b) {
    asm("fma.rn.f32x2 %0, %1, %2, %0;" : "+l"(d) : "l"(a), "l"(b));
}
__device__ __forceinline__ u64 mul2(u64 a, u64 b) {
    u64 r;
    asm("mul.rn.f32x2 %0, %1, %2;" : "=l"(r) : "l"(a), "l"(b));
    return r;
}
__device__ __forceinline__ u64 f2_bits(float2 v) {
    u64 r;
    asm("mov.b64 %0, {%1, %2};" : "=l"(r) : "f"(v.x), "f"(v.y));
    return r;
}
__device__ __forceinline__ float lo32(u64 a) {
    float r;
    asm("{ .reg .f32 hi; mov.b64 {%0, hi}, %1; }" : "=f"(r) : "l"(a));
    return r;
}
__device__ __forceinline__ float hi32(u64 a) {
    float r;
    asm("{ .reg .f32 lo; mov.b64 {lo, %0}, %1; }" : "=f"(r) : "l"(a));
    return r;
}

// ---------------------------------------------------------------------------
// Pyramid builder: grid (8, 8, 32), block 256. Level-1 pooled directly from
// coalesced float2 global loads; levels 2..4 via small SMEM stages.
// ---------------------------------------------------------------------------
__global__ __launch_bounds__(256)
void pyramid_kernel(const float* __restrict__ img1,
                    const float* __restrict__ img2,
                    float* __restrict__ buf1,
                    float* __restrict__ buf2,
                    double* __restrict__ sums)
{
    __shared__ float a1[32][33], a2[32][33];
    __shared__ float e1[16][17], e2[16][17];
    __shared__ float c1[8][9],  c2[8][9];

    const int tid = threadIdx.x;
    const int bx = blockIdx.x, by = blockIdx.y, b = blockIdx.z;

    if (bx == 0 && by == 0 && b == 0 && tid < 10) sums[tid] = 0.0;

    const float* __restrict__ p1 = img1 + (size_t)b * 512 * 512;
    const float* __restrict__ p2 = img2 + (size_t)b * 512 * 512;

    // level 1 (32x32 per block) straight from global float2 loads
#pragma unroll
    for (int it = 0; it < 4; it++) {
        const int o  = tid + 256 * it;
        const int oy = o >> 5, ox = o & 31;
        const size_t r0 = (size_t)(by * 64 + 2 * oy) * 512 + bx * 64 + 2 * ox;
        const float2 u0 = *(const float2*)(p1 + r0);
        const float2 u1 = *(const float2*)(p1 + r0 + 512);
        const float2 v0 = *(const float2*)(p2 + r0);
        const float2 v1 = *(const float2*)(p2 + r0 + 512);
        const float d1 = 0.25f * (u0.x + u0.y + u1.x + u1.y);
        const float d2 = 0.25f * (v0.x + v0.y + v1.x + v1.y);
        a1[oy][ox] = d1;
        a2[oy][ox] = d2;
        const size_t gi = ((size_t)b * 256 + (by * 32 + oy)) * 256 + (bx * 32 + ox);
        buf1[OFF1 + gi] = d1;
        buf2[OFF1 + gi] = d2;
    }
    __syncthreads();

    // level 2 (16x16)
    {
        const int oy = tid >> 4, ox = tid & 15;
        const float d1 = 0.25f * (a1[2*oy][2*ox] + a1[2*oy][2*ox+1] +
                                  a1[2*oy+1][2*ox] + a1[2*oy+1][2*ox+1]);
        const float d2 = 0.25f * (a2[2*oy][2*ox] + a2[2*oy][2*ox+1] +
                                  a2[2*oy+1][2*ox] + a2[2*oy+1][2*ox+1]);
        e1[oy][ox] = d1;
        e2[oy][ox] = d2;
        const size_t gi = ((size_t)b * 128 + (by * 16 + oy)) * 128 + (bx * 16 + ox);
        buf1[OFF2 + gi] = d1;
        buf2[OFF2 + gi] = d2;
    }
    __syncthreads();

    // level 3 (8x8)
    if (tid < 64) {
        const int oy = tid >> 3, ox = tid & 7;
        const float d1 = 0.25f * (e1[2*oy][2*ox] + e1[2*oy][2*ox+1] +
                                  e1[2*oy+1][2*ox] + e1[2*oy+1][2*ox+1]);
        const float d2 = 0.25f * (e2[2*oy][2*ox] + e2[2*oy][2*ox+1] +
                                  e2[2*oy+1][2*ox] + e2[2*oy+1][2*ox+1]);
        c1[oy][ox] = d1;
        c2[oy][ox] = d2;
        const size_t gi = ((size_t)b * 64 + (by * 8 + oy)) * 64 + (bx * 8 + ox);
        buf1[OFF3 + gi] = d1;
        buf2[OFF3 + gi] = d2;
    }
    __syncthreads();

    // level 4 (4x4)
    if (tid < 16) {
        const int oy = tid >> 2, ox = tid & 3;
        const float d1 = 0.25f * (c1[2*oy][2*ox] + c1[2*oy][2*ox+1] +
                                  c1[2*oy+1][2*ox] + c1[2*oy+1][2*ox+1]);
        const float d2 = 0.25f * (c2[2*oy][2*ox] + c2[2*oy][2*ox+1] +
                                  c2[2*oy+1][2*ox] + c2[2*oy+1][2*ox+1]);
        const size_t gi = ((size_t)b * 32 + (by * 4 + oy)) * 32 + (bx * 4 + ox);
        buf1[OFF4 + gi] = d1;
        buf2[OFF4 + gi] = d2;
    }
}

// ---------------------------------------------------------------------------
// All 5 SSIM levels, one flat grid, f32x2-packed blur math. Block (32,8).
// ---------------------------------------------------------------------------
__global__ __launch_bounds__(256, 5)
void ssim_all_kernel(const float* __restrict__ img1,
                     const float* __restrict__ img2,
                     const float* __restrict__ buf1,
                     const float* __restrict__ buf2,
                     double* __restrict__ sums)
{
    __shared__ float2 s12[SROWS][SSTR];         // (u, v) interleaved
    __shared__ u64    hb01[SROWS][HSTR];        // (mu1h, mu2h)
    __shared__ u64    hb23[SROWS][HSTR];        // (uuh, vvh)
    __shared__ float  hb4[SROWS][HSTR];         // uvh
    __shared__ float  wsum[8][2];

    const int tx  = threadIdx.x;
    const int ty  = threadIdx.y;
    const int tid = ty * 32 + tx;

    // decode level + tile coordinates from flat block id
    const int gb = blockIdx.x;
    int level, start;
    const float *p1base, *p2base;
    if (gb < 8192)       { level = 0; start = 0;     p1base = img1;        p2base = img2;        }
    else if (gb < 10240) { level = 1; start = 8192;  p1base = buf1 + OFF1; p2base = buf2 + OFF1; }
    else if (gb < 10752) { level = 2; start = 10240; p1base = buf1 + OFF2; p2base = buf2 + OFF2; }
    else if (gb < 10880) { level = 3; start = 10752; p1base = buf1 + OFF3; p2base = buf2 + OFF3; }
    else                 { level = 4; start = 10880; p1base = buf1 + OFF4; p2base = buf2 + OFF4; }

    const int shift = 4 - level;
    const int nbx   = 1 << shift;
    const int H     = 512 >> level;
    const int idx   = gb - start;
    const int b     = idx >> (2 * shift);
    const int rem   = idx & ((1 << (2 * shift)) - 1);
    const int byi   = rem >> shift;
    const int bxi   = rem & (nbx - 1);

    const int x0 = bxi * TILE - HALO;
    const int y0 = byi * TILE - HALO;

    const float* __restrict__ p1 = p1base + (size_t)b * H * H;
    const float* __restrict__ p2 = p2base + (size_t)b * H * H;

    // ---- load 42x42 halo tile (interleaved float2, zero pad = SAME) ----
    const bool interior = (x0 >= 0) && (y0 >= 0) &&
                          (x0 + SROWS <= H) && (y0 + SROWS <= H);
    if (interior) {
        for (int r = ty; r < SROWS; r += 8) {
            const size_t row = (size_t)(y0 + r) * H + x0;
#pragma unroll
            for (int c = tx; c < SROWS; c += TILE) {
                s12[r][c] = make_float2(p1[row + c], p2[row + c]);
            }
        }
    } else {
        for (int r = ty; r < SROWS; r += 8) {
            const int gy = y0 + r;
            const bool yok = (gy >= 0) && (gy < H);
#pragma unroll
            for (int c = tx; c < SROWS; c += TILE) {
                const int gx = x0 + c;
                float v1 = 0.f, v2 = 0.f;
                if (yok && gx >= 0 && gx < H) {
                    v1 = p1[(size_t)gy * H + gx];
                    v2 = p2[(size_t)gy * H + gx];
                }
                s12[r][c] = make_float2(v1, v2);
            }
        }
    }
    __syncthreads();

    // ---- horizontal 11-tap pass (packed): 42 rows x 8 col-groups of 4 ----
    for (int t = tid; t < SROWS * 8; t += 256) {
        const int r  = t >> 3;
        const int cg = (t & 7) << 2;
        const float2* __restrict__ brow = &s12[r][cg];

        u64 A01[4] = {0ull, 0ull, 0ull, 0ull};
        u64 A23[4] = {0ull, 0ull, 0ull, 0ull};
        float a4[4] = {0.f, 0.f, 0.f, 0.f};
#pragma unroll
        for (int i = 0; i < 14; i++) {
            const float2 p  = brow[i];
            const u64 uv    = f2_bits(p);
            const u64 sq    = mul2(uv, uv);       // (uu, vv)
            const float uvs = p.x * p.y;
#pragma unroll
            for (int j = 0; j < 4; j++) {
                const int k = i - j;
                if (k >= 0 && k < WIN) {
                    const u64 w2 = f2_bits(G2[k]);
                    fma2(A01[j], w2, uv);
                    fma2(A23[j], w2, sq);
                    a4[j] = fmaf(G11[k], uvs, a4[j]);
                }
            }
        }
#pragma unroll
        for (int j = 0; j < 4; j++) {
            hb01[r][cg + j] = A01[j];
            hb23[r][cg + j] = A23[j];
            hb4[r][cg + j]  = a4[j];
        }
    }
    __syncthreads();

    // ---- vertical 11-tap pass (packed): thread = col tx, rows 4*ty..+3 ----
    u64 V01[4] = {0ull, 0ull, 0ull, 0ull};
    u64 V23[4] = {0ull, 0ull, 0ull, 0ull};
    float v4[4] = {0.f, 0.f, 0.f, 0.f};

    const int r0 = ty << 2;
#pragma unroll
    for (int i = 0; i < 14; i++) {
        const u64 h01 = hb01[r0 + i][tx];
        const u64 h23 = hb23[r0 + i][tx];
        const float h4 = hb4[r0 + i][tx];
#pragma unroll
        for (int j = 0; j < 4; j++) {
            const int k = i - j;
            if (k >= 0 && k < WIN) {
                const u64 w2 = f2_bits(G2[k]);
                fma2(V01[j], w2, h01);
                fma2(V23[j], w2, h23);
                v4[j] = fmaf(G11[k], h4, v4[j]);
            }
        }
    }

    float lssim = 0.f, lmcs = 0.f;
#pragma unroll
    for (int j = 0; j < 4; j++) {
        const float m1  = lo32(V01[j]);
        const float m2  = hi32(V01[j]);
        const float m11 = lo32(V23[j]);
        const float m22 = hi32(V23[j]);
        const float m12 = v4[j];
        const float mu1sq = m1 * m1;
        const float mu2sq = m2 * m2;
        const float mu12  = m1 * m2;
        const float sig1  = m11 - mu1sq;
        const float sig2  = m22 - mu2sq;
        const float sig12 = m12 - mu12;
        const float mcs  = __fdividef(2.f * sig12 + C2F, sig1 + sig2 + C2F);
        const float ssim = __fdividef(2.f * mu12 + C1F, mu1sq + mu2sq + C1F) * mcs;
        lssim += ssim;
        lmcs  += mcs;
    }

    // ---- block reduction + per-level double atomics ----
#pragma unroll
    for (int o = 16; o > 0; o >>= 1) {
        lssim += __shfl_down_sync(0xffffffffu, lssim, o);
        lmcs  += __shfl_down_sync(0xffffffffu, lmcs,  o);
    }
    if (tx == 0) {
        wsum[ty][0] = lssim;
        wsum[ty][1] = lmcs;
    }
    __syncthreads();
    if (ty == 0 && tx < 8) {
        float a = wsum[tx][0];
        float c = wsum[tx][1];
#pragma unroll
        for (int o = 4; o > 0; o >>= 1) {
            a += __shfl_down_sync(0xffu, a, o);
            c += __shfl_down_sync(0xffu, c, o);
        }
        if (tx == 0) {
            atomicAdd(&sums[2 * level + 0], (double)a);
            atomicAdd(&sums[2 * level + 1], (double)c);
        }
    }
}

__global__ void finalize_kernel(const double* __restrict__ sums,
                                float* __restrict__ out)
{
    const double w[5] = {0.0448, 0.2856, 0.3001, 0.2363, 0.1333};
    double res = 1.0;
#pragma unroll
    for (int l = 0; l < 4; l++) {
        const double dim = (double)(512 >> l);
        const double N = 32.0 * dim * dim;
        const double mcs = sums[2 * l + 1] / N;
        res *= pow(mcs, w[l]);
    }
    {
        const double N = 32.0 * 32.0 * 32.0;
        const double ssim = sums[2 * 4 + 0] / N;
        res *= pow(ssim, w[4]);
    }
    out[0] = (float)res;
}

extern "C" void kernel_launch(void* const* d_in, const int* in_sizes, int n_in,
                              void* d_out, int out_size)
{
    const float* img1 = (const float*)d_in[0];
    const float* img2 = (const float*)d_in[1];
    float* out = (float*)d_out;

    double* sums = nullptr;
    float*  buf1 = nullptr;
    float*  buf2 = nullptr;
    cudaGetSymbolAddress((void**)&sums, g_sums);
    cudaGetSymbolAddress((void**)&buf1, g_buf1);
    cudaGetSymbolAddress((void**)&buf2, g_buf2);

    pyramid_kernel<<<dim3(8, 8, 32), 256>>>(img1, img2, buf1, buf2, sums);
    ssim_all_kernel<<<10912, dim3(32, 8)>>>(img1, img2, buf1, buf2, sums);
    finalize_kernel<<<1, 1>>>(sums, out);
}